// round 13
// baseline (speedup 1.0000x reference)
#include <cuda_runtime.h>
#include <cuda_bf16.h>
#include <cstdint>

// Problem constants
#define H   1024
#define B   64
#define S   512
#define W3H 3072            // W row stride (3*H)
#define CHUNK_ROWS 4        // rows per TMA chunk (16 KB)
#define CHUNK_BYTES (CHUNK_ROWS * H * 4)         // 16384
#define NCHUNKS_TOTAL ((B * S) / CHUNK_ROWS)     // 8192
#define CHUNKS_PER_B  (S / CHUNK_ROWS)           // 128
#define GRID 592            // 4 * 148 SMs: even 4-blocks/SM, all resident

// Scratch (zero-initialized at module load; every launch self-cleans, so each
// graph replay is deterministic).
__device__ float g_u2[H];
__device__ float g_scores[B * S];
__device__ int   g_cnt[B];           // per-b completed-chunk counters
__device__ int   g_gcnt;             // global softmax counter

// ---------------------------------------------------------------------------
// mbarrier / bulk-copy PTX helpers
// ---------------------------------------------------------------------------
__device__ __forceinline__ uint32_t smem_u32(const void* p) {
    return (uint32_t)__cvta_generic_to_shared(p);
}
__device__ __forceinline__ void mbar_init(uint32_t a, uint32_t cnt) {
    asm volatile("mbarrier.init.shared.b64 [%0], %1;" :: "r"(a), "r"(cnt) : "memory");
}
__device__ __forceinline__ void mbar_expect(uint32_t a, uint32_t bytes) {
    asm volatile("mbarrier.arrive.expect_tx.shared.b64 _, [%0], %1;"
                 :: "r"(a), "r"(bytes) : "memory");
}
__device__ __forceinline__ void bulk_g2s(uint32_t dst, const void* src,
                                         uint32_t bytes, uint32_t mbar) {
    asm volatile("cp.async.bulk.shared::cta.global.mbarrier::complete_tx::bytes "
                 "[%0], [%1], %2, [%3];"
                 :: "r"(dst), "l"(src), "r"(bytes), "r"(mbar) : "memory");
}
__device__ __forceinline__ void mbar_wait(uint32_t a, uint32_t parity) {
    uint32_t done;
    do {
        asm volatile("{\n\t.reg .pred p;\n\t"
                     "mbarrier.try_wait.parity.shared.b64 p, [%1], %2, 0x989680;\n\t"
                     "selp.b32 %0, 1, 0, p;\n\t}"
                     : "=r"(done) : "r"(a), "r"(parity) : "memory");
    } while (!done);
}
__device__ __forceinline__ void fence_async_smem() {
    asm volatile("fence.proxy.async.shared::cta;" ::: "memory");
}

// ---------------------------------------------------------------------------
// Kernel 1: u2[k] += sum_h v[h] * W[h, 2H + k]       (g_u2 pre-zeroed)
// grid = (4, 64): 256 blocks, 16 h-rows per block.
// ---------------------------------------------------------------------------
__global__ void k_u2(const float* __restrict__ W, const float* __restrict__ v) {
    const int tx = threadIdx.x & 63;
    const int ty = threadIdx.x >> 6;          // 0..3
    const int k4 = blockIdx.x * 64 + tx;
    const int h0 = blockIdx.y * 16 + ty;

    float4 acc = make_float4(0.f, 0.f, 0.f, 0.f);
#pragma unroll
    for (int j = 0; j < 4; j++) {
        const int h = h0 + j * 4;
        const float vh = __ldg(&v[h]);
        const float4 w = __ldg((const float4*)(W + (size_t)h * W3H + 2 * H) + k4);
        acc.x += vh * w.x; acc.y += vh * w.y; acc.z += vh * w.z; acc.w += vh * w.w;
    }

    __shared__ float4 sm[4][64];
    sm[ty][tx] = acc;
    __syncthreads();
    if (ty == 0) {
        float4 s = sm[0][tx];
#pragma unroll
        for (int j = 1; j < 4; j++) {
            const float4 p = sm[j][tx];
            s.x += p.x; s.y += p.y; s.z += p.z; s.w += p.w;
        }
        float* dst = g_u2 + k4 * 4;
        atomicAdd(dst + 0, s.x);
        atomicAdd(dst + 1, s.y);
        atomicAdd(dst + 2, s.z);
        atomicAdd(dst + 3, s.w);
    }
}

// ---------------------------------------------------------------------------
// Kernel 2: persistent grid-strided streaming (R8 microstructure unchanged).
// 592 blocks x 256 threads; block bid handles chunks bid, bid+592, ...
// (13-14 chunks each -> per-SM load ~55.4 chunks vs R8's 64-vs-48 imbalance).
// Per-chunk: tid0 writes 4 scores + fence + g_cnt[b]++; the block that
// completes a b's 128th chunk defers that b's softmax to after its loop.
// ---------------------------------------------------------------------------
__global__ void __launch_bounds__(256)
k_fused(const float* __restrict__ enc, float* __restrict__ out) {
    __shared__ alignas(128) float s_buf[2][CHUNK_ROWS][H];   // 32 KB
    __shared__ alignas(16)  float s_u2[H];                    // 4 KB
    __shared__ float s_part[CHUNK_ROWS][2];
    __shared__ alignas(8) unsigned long long s_mbar[2];
    __shared__ unsigned long long s_mask;   // b's whose softmax we owe
    __shared__ int s_last;                  // globally-last flag
    __shared__ float s_sm[256];

    const int tid  = threadIdx.x;
    const int warp = tid >> 5;
    const int lane = tid & 31;
    const int bid  = blockIdx.x;

    // stage u2 into smem (fresh via L2)
    ((float4*)s_u2)[tid] = __ldcg(((const float4*)g_u2) + tid);

    const uint32_t mb0 = smem_u32(&s_mbar[0]);
    const uint32_t mb1 = smem_u32(&s_mbar[1]);
    const uint32_t sb0 = smem_u32(&s_buf[0][0][0]);
    const uint32_t sb1 = smem_u32(&s_buf[1][0][0]);

    const int nIter = (NCHUNKS_TOTAL - bid + GRID - 1) / GRID;   // 13 or 14

    if (tid == 0) {
        s_mask = 0ull;
        mbar_init(mb0, 1);
        mbar_init(mb1, 1);
        fence_async_smem();
        mbar_expect(mb0, CHUNK_BYTES);
        bulk_g2s(sb0, enc + (size_t)bid * CHUNK_ROWS * H, CHUNK_BYTES, mb0);
        if (nIter > 1) {
            mbar_expect(mb1, CHUNK_BYTES);
            bulk_g2s(sb1, enc + (size_t)(bid + GRID) * CHUNK_ROWS * H,
                     CHUNK_BYTES, mb1);
        }
    }
    __syncthreads();

    const int r    = warp >> 1;        // row within chunk (0..3)
    const int half = warp & 1;         // which half of the row
    const int base = half * 512 + lane * 4;   // float index into row

    for (int it = 0; it < nIter; it++) {
        const int c = bid + it * GRID;             // global chunk id
        const uint32_t mb = (it & 1) ? mb1 : mb0;
        mbar_wait(mb, (it >> 1) & 1);

        const float* rowp = &s_buf[it & 1][r][0];
        float acc = 0.f;
#pragma unroll
        for (int k = 0; k < 4; k++) {
            const float4 e = *(const float4*)(rowp + base + k * 128);
            const float4 w = *(const float4*)(s_u2 + base + k * 128);
            acc += e.x * w.x + e.y * w.y + e.z * w.z + e.w * w.w;
        }
#pragma unroll
        for (int off = 16; off > 0; off >>= 1)
            acc += __shfl_xor_sync(0xffffffffu, acc, off);
        if (lane == 0) s_part[r][half] = acc;
        __syncthreads();                           // buffer reads + partials done

        if (tid == 0) {
            // refill this slot first (get TMA in flight ASAP)
            if (it + 2 < nIter) {
                fence_async_smem();
                mbar_expect(mb, CHUNK_BYTES);
                bulk_g2s((it & 1) ? sb1 : sb0,
                         enc + (size_t)(c + 2 * GRID) * CHUNK_ROWS * H,
                         CHUNK_BYTES, mb);
            }
            // single-thread score writes -> fence -> ticket (correct ordering)
            const int row0 = c * CHUNK_ROWS;
#pragma unroll
            for (int q = 0; q < CHUNK_ROWS; q++)
                g_scores[row0 + q] = s_part[q][0] + s_part[q][1];
            __threadfence();                       // release scores
            const int bb = c >> 7;                 // CHUNKS_PER_B = 128
            if (atomicAdd(&g_cnt[bb], 1) == CHUNKS_PER_B - 1)
                s_mask |= 1ull << bb;              // we owe this b's softmax
        }
        __syncthreads();
    }

    // ---- deferred softmaxes (usually 0, sometimes 1-2 per block) ----
    __syncthreads();
    unsigned long long mask = s_mask;
    if (mask == 0ull) return;

    if (tid == 0) __threadfence();                 // acquire released scores
    __syncthreads();

    while (mask) {
        const int b = __ffsll(mask) - 1;
        mask &= mask - 1;

        const float* sc = g_scores + b * S;
        const float v0 = __ldcg(&sc[tid]);
        const float v1 = __ldcg(&sc[tid + 256]);

        s_sm[tid] = fmaxf(v0, v1);
        __syncthreads();
#pragma unroll
        for (int st = 128; st > 0; st >>= 1) {
            if (tid < st) s_sm[tid] = fmaxf(s_sm[tid], s_sm[tid + st]);
            __syncthreads();
        }
        const float mx = s_sm[0];
        __syncthreads();

        const float e0 = __expf(v0 - mx);
        const float e1 = __expf(v1 - mx);
        s_sm[tid] = e0 + e1;
        __syncthreads();
#pragma unroll
        for (int st = 128; st > 0; st >>= 1) {
            if (tid < st) s_sm[tid] += s_sm[tid + st];
            __syncthreads();
        }
        const float inv = 1.f / s_sm[0];

        out[b * S + tid]       = e0 * inv;
        out[b * S + tid + 256] = e1 * inv;

        // --- self-clean for the next launch ---
        if (tid == 0) {
            g_cnt[b] = 0;
            __threadfence();
            const int g = atomicAdd(&g_gcnt, 1);
            s_last = (g == B - 1) ? 1 : 0;
        }
        __syncthreads();
        if (s_last) {
            // globally last softmax: u2 fully consumed by all blocks
            ((float4*)g_u2)[tid] = make_float4(0.f, 0.f, 0.f, 0.f);
            if (tid == 0) g_gcnt = 0;
        }
        __syncthreads();
    }
}

// ---------------------------------------------------------------------------
// Inputs (metadata order): hidden[2,B,H], encoder_outputs[B,S,H],
//                          W[H,3H], b[H], v[H]
// hidden and b are mathematically irrelevant post-softmax (per-row constants).
// ---------------------------------------------------------------------------
extern "C" void kernel_launch(void* const* d_in, const int* in_sizes, int n_in,
                              void* d_out, int out_size) {
    const float* enc = (const float*)d_in[1];
    const float* W   = (const float*)d_in[2];
    const float* v   = (const float*)d_in[4];
    float* out = (float*)d_out;

    {
        dim3 grid(4, 64);
        k_u2<<<grid, 256>>>(W, v);
    }
    k_fused<<<GRID, 256>>>(enc, out);
}

// round 14
// speedup vs baseline: 1.7354x; 1.7354x over previous
#include <cuda_runtime.h>
#include <cuda_bf16.h>
#include <cstdint>

// Problem constants
#define H   1024
#define B   64
#define S   512
#define W3H 3072            // W row stride (3*H)
#define BLKS_PER_B 8        // 8 blocks per batch entry
#define ROWS_PER_BLK 64     // rows per block
#define CHUNK_ROWS 4        // rows per TMA chunk
#define NCHUNK (ROWS_PER_BLK / CHUNK_ROWS)       // 16
#define CHUNK_BYTES (CHUNK_ROWS * H * 4)         // 16384

// Scratch (zero-initialized at module load; every launch self-cleans, so each
// graph replay is deterministic).
__device__ float g_u2[H];
__device__ float g_scores[B * S];
__device__ int   g_cnt[B];
__device__ int   g_gcnt;

// ---------------------------------------------------------------------------
// mbarrier / bulk-copy PTX helpers
// ---------------------------------------------------------------------------
__device__ __forceinline__ uint32_t smem_u32(const void* p) {
    return (uint32_t)__cvta_generic_to_shared(p);
}
__device__ __forceinline__ void mbar_init(uint32_t a, uint32_t cnt) {
    asm volatile("mbarrier.init.shared.b64 [%0], %1;" :: "r"(a), "r"(cnt) : "memory");
}
__device__ __forceinline__ void mbar_expect(uint32_t a, uint32_t bytes) {
    asm volatile("mbarrier.arrive.expect_tx.shared.b64 _, [%0], %1;"
                 :: "r"(a), "r"(bytes) : "memory");
}
__device__ __forceinline__ void bulk_g2s(uint32_t dst, const void* src,
                                         uint32_t bytes, uint32_t mbar) {
    asm volatile("cp.async.bulk.shared::cta.global.mbarrier::complete_tx::bytes "
                 "[%0], [%1], %2, [%3];"
                 :: "r"(dst), "l"(src), "r"(bytes), "r"(mbar) : "memory");
}
__device__ __forceinline__ void mbar_wait(uint32_t a, uint32_t parity) {
    uint32_t done;
    do {
        asm volatile("{\n\t.reg .pred p;\n\t"
                     "mbarrier.try_wait.parity.shared.b64 p, [%1], %2, 0x989680;\n\t"
                     "selp.b32 %0, 1, 0, p;\n\t}"
                     : "=r"(done) : "r"(a), "r"(parity) : "memory");
    } while (!done);
}
__device__ __forceinline__ void fence_async_smem() {
    asm volatile("fence.proxy.async.shared::cta;" ::: "memory");
}

// ---------------------------------------------------------------------------
// Kernel 1: u2[k] += sum_h v[h] * W[h, 2H + k]       (g_u2 pre-zeroed)
// grid = (4, 64): 256 blocks, 16 h-rows per block.
// ---------------------------------------------------------------------------
__global__ void k_u2(const float* __restrict__ W, const float* __restrict__ v) {
    const int tx = threadIdx.x & 63;
    const int ty = threadIdx.x >> 6;          // 0..3
    const int k4 = blockIdx.x * 64 + tx;
    const int h0 = blockIdx.y * 16 + ty;

    float4 acc = make_float4(0.f, 0.f, 0.f, 0.f);
#pragma unroll
    for (int j = 0; j < 4; j++) {
        const int h = h0 + j * 4;
        const float vh = __ldg(&v[h]);
        const float4 w = __ldg((const float4*)(W + (size_t)h * W3H + 2 * H) + k4);
        acc.x += vh * w.x; acc.y += vh * w.y; acc.z += vh * w.z; acc.w += vh * w.w;
    }

    __shared__ float4 sm[4][64];
    sm[ty][tx] = acc;
    __syncthreads();
    if (ty == 0) {
        float4 s = sm[0][tx];
#pragma unroll
        for (int j = 1; j < 4; j++) {
            const float4 p = sm[j][tx];
            s.x += p.x; s.y += p.y; s.z += p.z; s.w += p.w;
        }
        float* dst = g_u2 + k4 * 4;
        atomicAdd(dst + 0, s.x);
        atomicAdd(dst + 1, s.y);
        atomicAdd(dst + 2, s.z);
        atomicAdd(dst + 3, s.w);
    }
}

// ---------------------------------------------------------------------------
// Kernel 2: EXACT R8/R12 structure with ONE change: u2 lives in 16 registers
// per thread instead of smem. Crossbar traffic per chunk: 48KB -> 32KB.
// (At 6 TB/s target the crossbar needs TMA-write 41 + enc-read 41 + u2-read 41
//  = 123 B/cyc vs the 128 B/cyc limit — u2 reads were the marginal load.)
// ---------------------------------------------------------------------------
__global__ void __launch_bounds__(256)
k_fused(const float* __restrict__ enc, float* __restrict__ out) {
    __shared__ alignas(128) float s_buf[2][CHUNK_ROWS][H];   // 32 KB
    __shared__ float s_part[CHUNK_ROWS][2];
    __shared__ alignas(8) unsigned long long s_mbar[2];
    __shared__ int s_ticket;
    __shared__ float s_sm[256];

    const int tid  = threadIdx.x;
    const int warp = tid >> 5;
    const int lane = tid & 31;
    const int b    = blockIdx.x >> 3;
    const int row0 = blockIdx.x * ROWS_PER_BLK;

    const int r    = warp >> 1;        // row within chunk (0..3)
    const int half = warp & 1;         // which half of the row
    const int base = half * 512 + lane * 4;   // float index into row

    // u2 slice for this thread's fixed column indices -> 16 registers
    float4 u0 = __ldcg(((const float4*)g_u2) + (base >> 2));
    float4 u1 = __ldcg(((const float4*)g_u2) + (base >> 2) + 32);
    float4 u2r = __ldcg(((const float4*)g_u2) + (base >> 2) + 64);
    float4 u3 = __ldcg(((const float4*)g_u2) + (base >> 2) + 96);

    const uint32_t mb0 = smem_u32(&s_mbar[0]);
    const uint32_t mb1 = smem_u32(&s_mbar[1]);
    const uint32_t sb0 = smem_u32(&s_buf[0][0][0]);
    const uint32_t sb1 = smem_u32(&s_buf[1][0][0]);

    if (tid == 0) {
        mbar_init(mb0, 1);
        mbar_init(mb1, 1);
        fence_async_smem();
        mbar_expect(mb0, CHUNK_BYTES);
        bulk_g2s(sb0, enc + (size_t)row0 * H, CHUNK_BYTES, mb0);
        mbar_expect(mb1, CHUNK_BYTES);
        bulk_g2s(sb1, enc + (size_t)(row0 + CHUNK_ROWS) * H, CHUNK_BYTES, mb1);
    }
    __syncthreads();

    for (int c = 0; c < NCHUNK; c++) {
        const uint32_t mb = (c & 1) ? mb1 : mb0;
        mbar_wait(mb, (c >> 1) & 1);

        const float* rowp = &s_buf[c & 1][r][0];
        float acc = 0.f;
        {
            const float4 e0 = *(const float4*)(rowp + base);
            const float4 e1 = *(const float4*)(rowp + base + 128);
            const float4 e2 = *(const float4*)(rowp + base + 256);
            const float4 e3 = *(const float4*)(rowp + base + 384);
            acc += e0.x * u0.x + e0.y * u0.y + e0.z * u0.z + e0.w * u0.w;
            acc += e1.x * u1.x + e1.y * u1.y + e1.z * u1.z + e1.w * u1.w;
            acc += e2.x * u2r.x + e2.y * u2r.y + e2.z * u2r.z + e2.w * u2r.w;
            acc += e3.x * u3.x + e3.y * u3.y + e3.z * u3.z + e3.w * u3.w;
        }
#pragma unroll
        for (int off = 16; off > 0; off >>= 1)
            acc += __shfl_xor_sync(0xffffffffu, acc, off);
        if (lane == 0) s_part[r][half] = acc;
        __syncthreads();                      // buffer reads + partials done

        if (tid < CHUNK_ROWS)
            g_scores[row0 + c * CHUNK_ROWS + tid] = s_part[tid][0] + s_part[tid][1];

        if (tid == 0 && c + 2 < NCHUNK) {
            fence_async_smem();               // order smem reads before async reuse
            mbar_expect(mb, CHUNK_BYTES);
            bulk_g2s((c & 1) ? sb1 : sb0,
                     enc + (size_t)(row0 + (c + 2) * CHUNK_ROWS) * H,
                     CHUNK_BYTES, mb);
        }
    }

    // --- single-thread release + ticket ---
    __syncthreads();
    if (tid == 0) {
        __threadfence();
        s_ticket = atomicAdd(&g_cnt[b], 1);
        if (s_ticket == BLKS_PER_B - 1)
            __threadfence();                  // acquire for re-reads
    }
    __syncthreads();

    if (s_ticket == BLKS_PER_B - 1) {
        const float* sc = g_scores + b * S;
        const float v0 = __ldcg(&sc[tid]);
        const float v1 = __ldcg(&sc[tid + 256]);

        s_sm[tid] = fmaxf(v0, v1);
        __syncthreads();
#pragma unroll
        for (int st = 128; st > 0; st >>= 1) {
            if (tid < st) s_sm[tid] = fmaxf(s_sm[tid], s_sm[tid + st]);
            __syncthreads();
        }
        const float mx = s_sm[0];
        __syncthreads();

        const float e0 = __expf(v0 - mx);
        const float e1 = __expf(v1 - mx);
        s_sm[tid] = e0 + e1;
        __syncthreads();
#pragma unroll
        for (int st = 128; st > 0; st >>= 1) {
            if (tid < st) s_sm[tid] += s_sm[tid + st];
            __syncthreads();
        }
        const float inv = 1.f / s_sm[0];

        out[b * S + tid]       = e0 * inv;
        out[b * S + tid + 256] = e1 * inv;

        // --- self-clean for the next launch ---
        if (tid == 0) {
            g_cnt[b] = 0;
            __threadfence();
            const int g = atomicAdd(&g_gcnt, 1);
            s_ticket = (g == B - 1) ? 1 : 0;
        }
        __syncthreads();
        if (s_ticket == 1) {
            ((float4*)g_u2)[tid] = make_float4(0.f, 0.f, 0.f, 0.f);
            if (tid == 0) g_gcnt = 0;
        }
    }
}

// ---------------------------------------------------------------------------
// Inputs (metadata order): hidden[2,B,H], encoder_outputs[B,S,H],
//                          W[H,3H], b[H], v[H]
// hidden and b are mathematically irrelevant post-softmax (per-row constants).
// ---------------------------------------------------------------------------
extern "C" void kernel_launch(void* const* d_in, const int* in_sizes, int n_in,
                              void* d_out, int out_size) {
    const float* enc = (const float*)d_in[1];
    const float* W   = (const float*)d_in[2];
    const float* v   = (const float*)d_in[4];
    float* out = (float*)d_out;

    {
        dim3 grid(4, 64);
        k_u2<<<grid, 256>>>(W, v);
    }
    k_fused<<<B * BLKS_PER_B, 256>>>(enc, out);
}